// round 9
// baseline (speedup 1.0000x reference)
#include <cuda_runtime.h>
#include <cuda_fp16.h>
#include <cstdint>

#define D_  1024
#define H_  16
#define HD_ 64
#define T_  1024
#define B_  2
#define L_  8
#define FF_ 4096
#define V_  32000
#define M_  (B_ * T_)   // 2048 rows

// ---------------- scratch (device globals) ----------------------------------
__device__ __half g_wqkv[(size_t)L_ * D_ * 3 * D_];
__device__ __half g_wo  [(size_t)L_ * D_ * D_];
__device__ __half g_wf1 [(size_t)L_ * D_ * FF_];
__device__ __half g_wf2 [(size_t)L_ * FF_ * D_];
__device__ float g_x [M_ * D_];
__device__ __half g_q[M_ * D_];   // [BH,T,HD], pre-scaled
__device__ __half g_k[M_ * D_];   // [BH,T,HD]
__device__ __half g_v[M_ * D_];   // [BH,T,HD]
__device__ __half g_hh [M_ * D_];
__device__ __half g_oh [M_ * D_];
__device__ __half g_ffh[M_ * FF_];
__device__ float g_hf[B_ * D_];

// ---------------- ptx helpers ------------------------------------------------
__device__ __forceinline__ uint32_t smem_u32(const void* p) {
    uint32_t a;
    asm("{ .reg .u64 t; cvta.to.shared.u64 t, %1; cvt.u32.u64 %0, t; }" : "=r"(a) : "l"(p));
    return a;
}
#define LDSM4(r, a) \
    asm volatile("ldmatrix.sync.aligned.m8n8.x4.shared.b16 {%0,%1,%2,%3}, [%4];" \
        : "=r"((r)[0]), "=r"((r)[1]), "=r"((r)[2]), "=r"((r)[3]) : "r"(a))
#define LDSM4T(r, a) \
    asm volatile("ldmatrix.sync.aligned.m8n8.x4.trans.shared.b16 {%0,%1,%2,%3}, [%4];" \
        : "=r"((r)[0]), "=r"((r)[1]), "=r"((r)[2]), "=r"((r)[3]) : "r"(a))
#define MMA_F16(c, a, b) \
    asm volatile("mma.sync.aligned.m16n8k16.row.col.f32.f16.f16.f32 " \
        "{%0,%1,%2,%3}, {%4,%5,%6,%7}, {%8,%9}, {%0,%1,%2,%3};" \
        : "+f"((c)[0]), "+f"((c)[1]), "+f"((c)[2]), "+f"((c)[3]) \
        : "r"((a)[0]), "r"((a)[1]), "r"((a)[2]), "r"((a)[3]), "r"((b)[0]), "r"((b)[1]))
#define MMA_F16_2(c, a, b0, b1) \
    asm volatile("mma.sync.aligned.m16n8k16.row.col.f32.f16.f16.f32 " \
        "{%0,%1,%2,%3}, {%4,%5,%6,%7}, {%8,%9}, {%0,%1,%2,%3};" \
        : "+f"((c)[0]), "+f"((c)[1]), "+f"((c)[2]), "+f"((c)[3]) \
        : "r"((a)[0]), "r"((a)[1]), "r"((a)[2]), "r"((a)[3]), "r"(b0), "r"(b1))
#define CP_ASYNC16(d, g) \
    asm volatile("cp.async.cg.shared.global [%0], [%1], 16;" :: "r"(d), "l"(g))
#define CP_COMMIT() asm volatile("cp.async.commit_group;" ::: "memory")
#define CP_WAIT0()  asm volatile("cp.async.wait_group 0;" ::: "memory")
#define CP_WAIT1()  asm volatile("cp.async.wait_group 1;" ::: "memory")
#define CP_WAIT2()  asm volatile("cp.async.wait_group 2;" ::: "memory")

__device__ __forceinline__ uint32_t pack_h2(float a, float b) {
    __half2 h; h.x = __float2half_rn(a); h.y = __float2half_rn(b);
    return *(uint32_t*)&h;
}

// ---------------- embedding ---------------------------------------------------
__global__ void embed_k(const int* __restrict__ idx,
                        const float* __restrict__ tok,
                        const float* __restrict__ pos) {
    int m = blockIdx.x;
    int t = m & (T_ - 1);
    const float* te = tok + (size_t)idx[m] * D_;
    const float* pe = pos + (size_t)t * D_;
    float* xr = g_x + (size_t)m * D_;
    for (int d = threadIdx.x; d < D_; d += blockDim.x)
        xr[d] = te[d] + pe[d];
}

// ---------------- weight convert ----------------------------------------------
__global__ void convw1(const float* __restrict__ W, __half* __restrict__ hi) {
    size_t idx = ((size_t)blockIdx.x * 256 + threadIdx.x) * 8;
    float4 v0 = *(const float4*)(W + idx);
    float4 v1 = *(const float4*)(W + idx + 4);
    union { uint4 u; __half b[8]; } ph;
    ph.b[0] = __float2half_rn(v0.x); ph.b[1] = __float2half_rn(v0.y);
    ph.b[2] = __float2half_rn(v0.z); ph.b[3] = __float2half_rn(v0.w);
    ph.b[4] = __float2half_rn(v1.x); ph.b[5] = __float2half_rn(v1.y);
    ph.b[6] = __float2half_rn(v1.z); ph.b[7] = __float2half_rn(v1.w);
    *(uint4*)(hi + idx) = ph.u;
}

__global__ void convqkv(const float* __restrict__ W, int colOff,
                        __half* __restrict__ hi) {
    long z = blockIdx.y;
    long idx = ((long)blockIdx.x * 256 + threadIdx.x) * 4;
    int k = (int)(idx >> 10);
    int n = (int)(idx & 1023);
    float4 v = *(const float4*)(W + z * (1 << 20) + idx);
    size_t d = (size_t)z * (3 << 20) + (size_t)k * (3 * D_) + colOff + n;
    union { uint2 u; __half b[4]; } ph;
    ph.b[0] = __float2half_rn(v.x); ph.b[1] = __float2half_rn(v.y);
    ph.b[2] = __float2half_rn(v.z); ph.b[3] = __float2half_rn(v.w);
    *(uint2*)(hi + d) = ph.u;
}

// ---------------- layernorm ----------------------------------------------------
__global__ void ln_k(const float* __restrict__ in, long in_stride,
                     const float* __restrict__ w, const float* __restrict__ b,
                     __half* __restrict__ oh, float* __restrict__ of) {
    const float* row = in + (size_t)blockIdx.x * in_stride;
    int tid = threadIdx.x;
    float vals[4];
    float s = 0.f;
    #pragma unroll
    for (int i = 0; i < 4; i++) { vals[i] = row[tid + 256 * i]; s += vals[i]; }

    __shared__ float red[8];
    int lane = tid & 31, warp = tid >> 5;
    #pragma unroll
    for (int off = 16; off; off >>= 1) s += __shfl_xor_sync(0xffffffffu, s, off);
    if (lane == 0) red[warp] = s;
    __syncthreads();
    float tot = 0.f;
    #pragma unroll
    for (int i = 0; i < 8; i++) tot += red[i];
    float mean = tot * (1.0f / D_);

    float s2 = 0.f;
    #pragma unroll
    for (int i = 0; i < 4; i++) { float d = vals[i] - mean; s2 += d * d; }
    __syncthreads();
    #pragma unroll
    for (int off = 16; off; off >>= 1) s2 += __shfl_xor_sync(0xffffffffu, s2, off);
    if (lane == 0) red[warp] = s2;
    __syncthreads();
    float tot2 = 0.f;
    #pragma unroll
    for (int i = 0; i < 8; i++) tot2 += red[i];
    float inv = rsqrtf(tot2 * (1.0f / D_) + 1e-5f);

    size_t base = (size_t)blockIdx.x * D_;
    #pragma unroll
    for (int i = 0; i < 4; i++) {
        int d = tid + 256 * i;
        float v = (vals[i] - mean) * inv * w[d] + b[d];
        if (of) of[base + d] = v;
        if (oh) oh[base + d] = __float2half_rn(v);
    }
}

// ---------------- mma.sync fp16 GEMM, BMx128x32, 4-stage, 2 CTA/SM -------------
#define B_TILE 8704                         // 32 rows x 272B

template<int MODE, int BM>
__global__ __launch_bounds__(256, 2)
void gemm_tc(const __half* __restrict__ A, const __half* __restrict__ Bw,
             const float* __restrict__ bias0, const float* __restrict__ bias1,
             const float* __restrict__ bias2, const float* __restrict__ res,
             float* __restrict__ Cf, __half* __restrict__ Ch,
             __half* p0, __half* p1, __half* p2,
             int Kdim, int Nb, int Nout) {
    constexpr int MI     = BM / 32;
    constexpr int A_TILE = BM * 80;
    constexpr int STAGE  = A_TILE + B_TILE;

    extern __shared__ char smem[];
    const uint32_t sb = smem_u32(smem);
    const int tid = threadIdx.x, lane = tid & 31, wid = tid >> 5;
    const int bm = blockIdx.y * BM, bn = blockIdx.x * 128;
    const int wm = wid & 1, wn = wid >> 1;

    const int KT = Kdim >> 5;

    auto load_stage = [&](int ss) {
        const uint32_t dst = sb + (ss & 3) * STAGE;
        const int kg = ss * 32;
        #pragma unroll
        for (int i = 0; i < BM / 64; i++) {
            int ch = tid + 256 * i;
            int r = ch >> 2;
            const __half* ga = A + (size_t)(bm + r) * Kdim + kg + (ch & 3) * 8;
            CP_ASYNC16(dst + r * 80 + (ch & 3) * 16, ga);
        }
        #pragma unroll
        for (int i = 0; i < 2; i++) {
            int ch = tid + 256 * i;
            int r = ch >> 4, c = (ch & 15) * 8;
            const __half* gb = Bw + (size_t)(kg + r) * Nb + bn + c;
            CP_ASYNC16(dst + A_TILE + r * 272 + (ch & 15) * 16, gb);
        }
    };

    load_stage(0); CP_COMMIT();
    load_stage(1); CP_COMMIT();
    load_stage(2); CP_COMMIT();

    float acc[MI][4][4] = {};

    for (int s = 0; s < KT; s++) {
        const int pend = KT - 1 - s;
        if (pend >= 2)      { CP_WAIT2(); }
        else if (pend == 1) { CP_WAIT1(); }
        else                { CP_WAIT0(); }
        __syncthreads();
        if (s + 3 < KT) { load_stage(s + 3); CP_COMMIT(); }

        const uint32_t base = sb + (s & 3) * STAGE;
        #pragma unroll
        for (int ks = 0; ks < 2; ks++) {
            uint32_t ah[MI][4], bh[2][4];
            #pragma unroll
            for (int mi = 0; mi < MI; mi++) {
                uint32_t ra = base + (wm * (BM / 2) + mi * 16 + (lane & 15)) * 80
                            + ks * 32 + (lane >> 4) * 16;
                LDSM4(ah[mi], ra);
            }
            #pragma unroll
            for (int g = 0; g < 2; g++) {
                uint32_t rb = base + A_TILE + (ks * 16 + (lane & 15)) * 272
                            + (wn * 32 + g * 16) * 2 + (lane >> 4) * 16;
                LDSM4T(bh[g], rb);
            }
            #pragma unroll
            for (int mi = 0; mi < MI; mi++)
                #pragma unroll
                for (int ni = 0; ni < 4; ni++) {
                    const uint32_t* bhp = &bh[ni >> 1][(ni & 1) * 2];
                    MMA_F16(acc[mi][ni], ah[mi], bhp);
                }
        }
    }

    // epilogue
    #pragma unroll
    for (int mi = 0; mi < MI; mi++) {
        const int r0 = bm + wm * (BM / 2) + mi * 16 + (lane >> 2);
        #pragma unroll
        for (int rr = 0; rr < 2; rr++) {
            const int m = r0 + rr * 8;
            const int bt = m >> 10, tt = m & (T_ - 1);
            #pragma unroll
            for (int ni = 0; ni < 4; ni++) {
                const int cc = bn + wn * 32 + ni * 8 + (lane & 3) * 2;
                float v0 = acc[mi][ni][rr * 2 + 0];
                float v1 = acc[mi][ni][rr * 2 + 1];
                if (MODE == 0) {
                    const int which = cc >> 10;
                    const int nn = cc & 1023;
                    const float* bp = (which == 0) ? bias0 : (which == 1 ? bias1 : bias2);
                    const int h = nn >> 6, hd = nn & 63;
                    const int bh_ = bt * H_ + h;
                    v0 += bp[nn]; v1 += bp[nn + 1];
                    if (which == 0) { v0 *= 0.125f; v1 *= 0.125f; }
                    __half2 hh;
                    hh.x = __float2half_rn(v0); hh.y = __float2half_rn(v1);
                    __half* dst = (which == 0) ? p0 : (which == 1 ? p1 : p2);
                    size_t o = ((size_t)bh_ * T_ + tt) * HD_ + hd;
                    *(__half2*)(dst + o) = hh;
                } else if (MODE == 1) {
                    size_t idx = (size_t)m * Nout + cc;
                    float2 bv = *(const float2*)(bias0 + cc);
                    float2 rv = *(const float2*)(res + idx);
                    float2 o2 = {v0 + bv.x + rv.x, v1 + bv.y + rv.y};
                    *(float2*)(Cf + idx) = o2;
                } else {
                    size_t idx = (size_t)m * Nout + cc;
                    float2 bv = *(const float2*)(bias0 + cc);
                    __half2 hh;
                    hh.x = __float2half_rn(fmaxf(v0 + bv.x, 0.f));
                    hh.y = __float2half_rn(fmaxf(v1 + bv.y, 0.f));
                    *(__half2*)(Ch + idx) = hh;
                }
            }
        }
    }
}

// ---------------- tensor-core flash attention ----------------------------------
// Q/K/V all [BH,T,HD]. K B-frags via non-trans ldmatrix ([n][k] rows = B layout).
// Tile index reversed so heavy (low-index→high work? no: high tile = more K tiles)
// CTAs with the most work launch first.
#define APAD 72
#define ATILE_H (64 * APAD)
#define ATT_SMEM (3 * ATILE_H * 2)   // 27648 bytes

__global__ __launch_bounds__(128)
void attn_k(const __half* __restrict__ qg, const __half* __restrict__ kg,
            const __half* __restrict__ vg, __half* __restrict__ oh) {
    extern __shared__ __half as_[];
    __half* Qs = as_;
    __half* Ks = Qs + ATILE_H;
    __half* Vs = Ks + ATILE_H;

    const int tid = threadIdx.x, lane = tid & 31, warp = tid >> 5;
    const int bh = blockIdx.y;
    const int qt = gridDim.x - 1 - blockIdx.x;   // heavy tiles first
    const int q0 = qt * 64;
    const int b = bh >> 4, h = bh & 15;

    #pragma unroll
    for (int i = 0; i < 4; i++) {
        int ch = tid + 128 * i;
        int r = ch >> 3, c = (ch & 7) * 8;
        *(uint4*)&Qs[r * APAD + c] =
            *(const uint4*)(qg + ((size_t)bh * T_ + q0 + r) * HD_ + c);
    }
    __syncthreads();

    uint32_t aq[4][4];
    const uint32_t qbase = smem_u32(Qs);
    #pragma unroll
    for (int kf = 0; kf < 4; kf++) {
        uint32_t ra = qbase + ((warp * 16 + (lane & 15)) * APAD + kf * 16 + (lane >> 4) * 8) * 2;
        LDSM4(aq[kf], ra);
    }

    float mx[2] = {-1e30f, -1e30f}, lsum[2] = {0.f, 0.f};
    float oacc[8][4] = {};

    const uint32_t kbase = smem_u32(Ks);
    const uint32_t vbase = smem_u32(Vs);
    const int ntiles = qt + 1;

    for (int jt = 0; jt < ntiles; jt++) {
        const int j0 = jt * 64;
        __syncthreads();
        #pragma unroll
        for (int i = 0; i < 4; i++) {
            int ch = tid + 128 * i;
            int r = ch >> 3, c = (ch & 7) * 8;
            size_t g = ((size_t)bh * T_ + j0 + r) * HD_ + c;
            *(uint4*)&Ks[r * APAD + c] = *(const uint4*)(kg + g);
            *(uint4*)&Vs[r * APAD + c] = *(const uint4*)(vg + g);
        }
        __syncthreads();

        // scores: S = Q . K^T ; K rows are keys ([n][k]) -> non-trans ldmatrix
        float sacc[8][4] = {};
        #pragma unroll
        for (int g = 0; g < 4; g++) {           // key group of 16
            #pragma unroll
            for (int kf = 0; kf < 4; kf++) {    // hd k-step of 16
                uint32_t kb[4];
                uint32_t rb = kbase + ((g * 16 + (lane & 15)) * APAD + kf * 16 + (lane >> 4) * 8) * 2;
                LDSM4(kb, rb);
                // b for n0-7: {kb[0],kb[2]}, n8-15: {kb[1],kb[3]}
                MMA_F16_2(sacc[2 * g],     aq[kf], kb[0], kb[2]);
                MMA_F16_2(sacc[2 * g + 1], aq[kf], kb[1], kb[3]);
            }
        }

        if (jt == qt) {
            const int rbase = q0 + warp * 16 + (lane >> 2);
            #pragma unroll
            for (int nf = 0; nf < 8; nf++) {
                int c0 = j0 + nf * 8 + (lane & 3) * 2;
                if (c0     > rbase)     sacc[nf][0] = -1e30f;
                if (c0 + 1 > rbase)     sacc[nf][1] = -1e30f;
                if (c0     > rbase + 8) sacc[nf][2] = -1e30f;
                if (c0 + 1 > rbase + 8) sacc[nf][3] = -1e30f;
            }
        }

        #pragma unroll
        for (int hf = 0; hf < 2; hf++) {
            float mnew = -1e30f;
            #pragma unroll
            for (int nf = 0; nf < 8; nf++)
                mnew = fmaxf(mnew, fmaxf(sacc[nf][hf * 2], sacc[nf][hf * 2 + 1]));
            mnew = fmaxf(mnew, __shfl_xor_sync(0xffffffffu, mnew, 1));
            mnew = fmaxf(mnew, __shfl_xor_sync(0xffffffffu, mnew, 2));
            float mn = fmaxf(mx[hf], mnew);
            float corr = __expf(mx[hf] - mn);
            float ps = 0.f;
            #pragma unroll
            for (int nf = 0; nf < 8; nf++) {
                float s0 = __expf(sacc[nf][hf * 2]     - mn);
                float s1 = __expf(sacc[nf][hf * 2 + 1] - mn);
                sacc[nf][hf * 2] = s0; sacc[nf][hf * 2 + 1] = s1;
                ps += s0 + s1;
            }
            ps += __shfl_xor_sync(0xffffffffu, ps, 1);
            ps += __shfl_xor_sync(0xffffffffu, ps, 2);
            lsum[hf] = lsum[hf] * corr + ps;
            #pragma unroll
            for (int nf = 0; nf < 8; nf++) {
                oacc[nf][hf * 2] *= corr; oacc[nf][hf * 2 + 1] *= corr;
            }
            mx[hf] = mn;
        }

        uint32_t pah[4][4];
        #pragma unroll
        for (int kf = 0; kf < 4; kf++) {
            const float* s0 = sacc[2 * kf];
            const float* s1 = sacc[2 * kf + 1];
            pah[kf][0] = pack_h2(s0[0], s0[1]);
            pah[kf][1] = pack_h2(s0[2], s0[3]);
            pah[kf][2] = pack_h2(s1[0], s1[1]);
            pah[kf][3] = pack_h2(s1[2], s1[3]);
        }

        // O += P . V  (V rows are keys = k -> trans ldmatrix, as before)
        #pragma unroll
        for (int kf = 0; kf < 4; kf++) {
            #pragma unroll
            for (int g = 0; g < 4; g++) {
                uint32_t vb2[4];
                uint32_t rb = vbase + ((kf * 16 + (lane & 15)) * APAD + g * 16 + (lane >> 4) * 8) * 2;
                LDSM4T(vb2, rb);
                MMA_F16(oacc[2 * g],     pah[kf], vb2);
                MMA_F16(oacc[2 * g + 1], pah[kf], vb2 + 2);
            }
        }
    }

    #pragma unroll
    for (int hf = 0; hf < 2; hf++) {
        float inv = 1.0f / lsum[hf];
        int row = q0 + warp * 16 + (lane >> 2) + hf * 8;
        size_t rbase = ((size_t)(b * T_ + row)) * D_ + h * HD_;
        #pragma unroll
        for (int nf = 0; nf < 8; nf++) {
            int col = nf * 8 + (lane & 3) * 2;
            __half2 o2;
            o2.x = __float2half_rn(oacc[nf][hf * 2]     * inv);
            o2.y = __float2half_rn(oacc[nf][hf * 2 + 1] * inv);
            *(__half2*)(oh + rbase + col) = o2;
        }
    }
}

// ---------------- head GEMV ------------------------------------------------------
__global__ __launch_bounds__(256)
void head_k(const float* __restrict__ hf, const float* __restrict__ W,
            const float* __restrict__ hb, float* __restrict__ out) {
    __shared__ float s0[D_];
    __shared__ float s1[D_];
    for (int i = threadIdx.x; i < D_; i += 256) { s0[i] = hf[i]; s1[i] = hf[D_ + i]; }
    __syncthreads();
    int vcol = blockIdx.x * 256 + threadIdx.x;
    float a0 = 0.f, a1 = 0.f;
    #pragma unroll 4
    for (int d = 0; d < D_; d++) {
        float wv = W[(size_t)d * V_ + vcol];
        a0 += s0[d] * wv;
        a1 += s1[d] * wv;
    }
    float bb = hb[vcol];
    out[vcol]      = a0 + bb;
    out[V_ + vcol] = a1 + bb;
}

// ---------------- launch --------------------------------------------------
extern "C" void kernel_launch(void* const* d_in, const int* in_sizes, int n_in,
                              void* d_out, int out_size) {
    const int*   idx    = (const int*)  d_in[0];
    const float* tok    = (const float*)d_in[1];
    const float* pos    = (const float*)d_in[2];
    const float* ln1w   = (const float*)d_in[3];
    const float* ln1b   = (const float*)d_in[4];
    const float* qw     = (const float*)d_in[5];
    const float* qb     = (const float*)d_in[6];
    const float* kw     = (const float*)d_in[7];
    const float* kbi    = (const float*)d_in[8];
    const float* vw     = (const float*)d_in[9];
    const float* vb     = (const float*)d_in[10];
    const float* ow     = (const float*)d_in[11];
    const float* ob     = (const float*)d_in[12];
    const float* ln2w   = (const float*)d_in[13];
    const float* ln2b   = (const float*)d_in[14];
    const float* f1w    = (const float*)d_in[15];
    const float* f1b    = (const float*)d_in[16];
    const float* f2w    = (const float*)d_in[17];
    const float* f2b    = (const float*)d_in[18];
    const float* lnfw   = (const float*)d_in[19];
    const float* lnfb   = (const float*)d_in[20];
    const float* headw  = (const float*)d_in[21];
    const float* headb  = (const float*)d_in[22];

    float *x, *hf;
    __half *wqkv, *wo, *wf1, *wf2, *q, *k, *v, *hh, *oh, *ffh;
    cudaGetSymbolAddress((void**)&x,    g_x);
    cudaGetSymbolAddress((void**)&hf,   g_hf);
    cudaGetSymbolAddress((void**)&wqkv, g_wqkv);
    cudaGetSymbolAddress((void**)&wo,   g_wo);
    cudaGetSymbolAddress((void**)&wf1,  g_wf1);
    cudaGetSymbolAddress((void**)&wf2,  g_wf2);
    cudaGetSymbolAddress((void**)&q,    g_q);
    cudaGetSymbolAddress((void**)&k,    g_k);
    cudaGetSymbolAddress((void**)&v,    g_v);
    cudaGetSymbolAddress((void**)&hh,   g_hh);
    cudaGetSymbolAddress((void**)&oh,   g_oh);
    cudaGetSymbolAddress((void**)&ffh,  g_ffh);

    const int GS128 = 4 * (128 * 80 + B_TILE);   // 75776
    const int GS64  = 4 * (64 * 80 + B_TILE);    // 55296
    cudaFuncSetAttribute(gemm_tc<0, 128>, cudaFuncAttributeMaxDynamicSharedMemorySize, GS128);
    cudaFuncSetAttribute(gemm_tc<1, 64>,  cudaFuncAttributeMaxDynamicSharedMemorySize, GS64);
    cudaFuncSetAttribute(gemm_tc<2, 128>, cudaFuncAttributeMaxDynamicSharedMemorySize, GS128);
    cudaFuncSetAttribute(attn_k, cudaFuncAttributeMaxDynamicSharedMemorySize, ATT_SMEM);

    const long MEG = 1024 * 1024;
    dim3 gQKV(24, 16), gDD(8, 32), gF1(32, 16);
    dim3 gAt(T_ / 64, B_ * H_);

    embed_k<<<M_, 256>>>(idx, tok, pos);
    convqkv<<<dim3(1024, L_), 256>>>(qw, 0,    wqkv);
    convqkv<<<dim3(1024, L_), 256>>>(kw, 1024, wqkv);
    convqkv<<<dim3(1024, L_), 256>>>(vw, 2048, wqkv);
    ln_k<<<M_, 256>>>(x, D_, ln1w, ln1b, hh, nullptr);
    gemm_tc<0, 128><<<gQKV, 256, GS128>>>(hh, wqkv, qb, kbi, vb, nullptr,
                                          nullptr, nullptr, q, k, v, D_, 3 * D_, 0);
    convw1<<<(L_ * MEG) / 2048, 256>>>(ow,  wo);
    convw1<<<(L_ * 4 * MEG) / 2048, 256>>>(f1w, wf1);
    convw1<<<(L_ * 4 * MEG) / 2048, 256>>>(f2w, wf2);

    for (int l = 0; l < L_; l++) {
        size_t wq3 = (size_t)l * 3 * MEG;
        size_t wdd = (size_t)l * MEG;
        size_t wff = (size_t)l * 4 * MEG;

        if (l > 0) {
            ln_k<<<M_, 256>>>(x, D_, ln1w + l * D_, ln1b + l * D_, hh, nullptr);
            gemm_tc<0, 128><<<gQKV, 256, GS128>>>(hh, wqkv + wq3,
                                                  qb + l * D_, kbi + l * D_, vb + l * D_,
                                                  nullptr, nullptr, nullptr,
                                                  q, k, v, D_, 3 * D_, 0);
        }

        attn_k<<<gAt, 128, ATT_SMEM>>>(q, k, v, oh);

        gemm_tc<1, 64><<<gDD, 256, GS64>>>(oh, wo + wdd,
                                           ob + l * D_, nullptr, nullptr, x,
                                           x, nullptr, nullptr, nullptr, nullptr,
                                           D_, D_, D_);

        ln_k<<<M_, 256>>>(x, D_, ln2w + l * D_, ln2b + l * D_, hh, nullptr);

        gemm_tc<2, 128><<<gF1, 256, GS128>>>(hh, wf1 + wff,
                                             f1b + l * FF_, nullptr, nullptr, nullptr,
                                             nullptr, ffh, nullptr, nullptr, nullptr,
                                             D_, FF_, FF_);

        gemm_tc<1, 64><<<gDD, 256, GS64>>>(ffh, wf2 + wff,
                                           f2b + l * D_, nullptr, nullptr, x,
                                           x, nullptr, nullptr, nullptr, nullptr,
                                           FF_, D_, D_);
    }

    ln_k<<<B_, 256>>>(x + (size_t)(T_ - 1) * D_, (long)T_ * D_, lnfw, lnfb,
                      nullptr, hf);

    head_k<<<V_ / 256, 256>>>(hf, headw, headb, (float*)d_out);
}

// round 10
// speedup vs baseline: 1.0036x; 1.0036x over previous
#include <cuda_runtime.h>
#include <cuda_fp16.h>
#include <cstdint>

#define D_  1024
#define H_  16
#define HD_ 64
#define T_  1024
#define B_  2
#define L_  8
#define FF_ 4096
#define V_  32000
#define M_  (B_ * T_)   // 2048 rows

// ---------------- scratch (device globals) ----------------------------------
__device__ __half g_wqkv[(size_t)L_ * D_ * 3 * D_];
__device__ __half g_wo  [(size_t)L_ * D_ * D_];
__device__ __half g_wf1 [(size_t)L_ * D_ * FF_];
__device__ __half g_wf2 [(size_t)L_ * FF_ * D_];
__device__ float g_x [M_ * D_];
__device__ __half g_q[M_ * D_];   // [BH,T,HD], pre-scaled
__device__ __half g_k[M_ * D_];   // [BH,T,HD]
__device__ __half g_v[M_ * D_];   // [BH,T,HD]
__device__ __half g_hh [M_ * D_];
__device__ __half g_oh [M_ * D_];
__device__ __half g_ffh[M_ * FF_];
__device__ float g_hf[B_ * D_];

// ---------------- ptx helpers ------------------------------------------------
__device__ __forceinline__ uint32_t smem_u32(const void* p) {
    uint32_t a;
    asm("{ .reg .u64 t; cvta.to.shared.u64 t, %1; cvt.u32.u64 %0, t; }" : "=r"(a) : "l"(p));
    return a;
}
#define LDSM4(r, a) \
    asm volatile("ldmatrix.sync.aligned.m8n8.x4.shared.b16 {%0,%1,%2,%3}, [%4];" \
        : "=r"((r)[0]), "=r"((r)[1]), "=r"((r)[2]), "=r"((r)[3]) : "r"(a))
#define LDSM4T(r, a) \
    asm volatile("ldmatrix.sync.aligned.m8n8.x4.trans.shared.b16 {%0,%1,%2,%3}, [%4];" \
        : "=r"((r)[0]), "=r"((r)[1]), "=r"((r)[2]), "=r"((r)[3]) : "r"(a))
#define MMA_F16(c, a, b) \
    asm volatile("mma.sync.aligned.m16n8k16.row.col.f32.f16.f16.f32 " \
        "{%0,%1,%2,%3}, {%4,%5,%6,%7}, {%8,%9}, {%0,%1,%2,%3};" \
        : "+f"((c)[0]), "+f"((c)[1]), "+f"((c)[2]), "+f"((c)[3]) \
        : "r"((a)[0]), "r"((a)[1]), "r"((a)[2]), "r"((a)[3]), "r"((b)[0]), "r"((b)[1]))
#define MMA_F16_2(c, a, b0, b1) \
    asm volatile("mma.sync.aligned.m16n8k16.row.col.f32.f16.f16.f32 " \
        "{%0,%1,%2,%3}, {%4,%5,%6,%7}, {%8,%9}, {%0,%1,%2,%3};" \
        : "+f"((c)[0]), "+f"((c)[1]), "+f"((c)[2]), "+f"((c)[3]) \
        : "r"((a)[0]), "r"((a)[1]), "r"((a)[2]), "r"((a)[3]), "r"(b0), "r"(b1))
#define CP_ASYNC16(d, g) \
    asm volatile("cp.async.cg.shared.global [%0], [%1], 16;" :: "r"(d), "l"(g))
#define CP_COMMIT() asm volatile("cp.async.commit_group;" ::: "memory")
#define CP_WAIT0()  asm volatile("cp.async.wait_group 0;" ::: "memory")
#define CP_WAIT1()  asm volatile("cp.async.wait_group 1;" ::: "memory")

__device__ __forceinline__ uint32_t pack_h2(float a, float b) {
    __half2 h; h.x = __float2half_rn(a); h.y = __float2half_rn(b);
    return *(uint32_t*)&h;
}

// ---------------- embedding ---------------------------------------------------
__global__ void embed_k(const int* __restrict__ idx,
                        const float* __restrict__ tok,
                        const float* __restrict__ pos) {
    int m = blockIdx.x;
    int t = m & (T_ - 1);
    const float* te = tok + (size_t)idx[m] * D_;
    const float* pe = pos + (size_t)t * D_;
    float* xr = g_x + (size_t)m * D_;
    for (int d = threadIdx.x; d < D_; d += blockDim.x)
        xr[d] = te[d] + pe[d];
}

// ---------------- weight convert ----------------------------------------------
__global__ void convw1(const float* __restrict__ W, __half* __restrict__ hi) {
    size_t idx = ((size_t)blockIdx.x * 256 + threadIdx.x) * 8;
    float4 v0 = *(const float4*)(W + idx);
    float4 v1 = *(const float4*)(W + idx + 4);
    union { uint4 u; __half b[8]; } ph;
    ph.b[0] = __float2half_rn(v0.x); ph.b[1] = __float2half_rn(v0.y);
    ph.b[2] = __float2half_rn(v0.z); ph.b[3] = __float2half_rn(v0.w);
    ph.b[4] = __float2half_rn(v1.x); ph.b[5] = __float2half_rn(v1.y);
    ph.b[6] = __float2half_rn(v1.z); ph.b[7] = __float2half_rn(v1.w);
    *(uint4*)(hi + idx) = ph.u;
}

// merged QKV conversion: z selects source (0=q,1=k,2=v), y = layer
__global__ void convqkv(const float* __restrict__ qw, const float* __restrict__ kw,
                        const float* __restrict__ vw, __half* __restrict__ hi) {
    const float* W = (blockIdx.z == 0) ? qw : (blockIdx.z == 1 ? kw : vw);
    const int colOff = blockIdx.z << 10;
    long z = blockIdx.y;
    long idx = ((long)blockIdx.x * 256 + threadIdx.x) * 4;
    int k = (int)(idx >> 10);
    int n = (int)(idx & 1023);
    float4 v = *(const float4*)(W + z * (1 << 20) + idx);
    size_t d = (size_t)z * (3 << 20) + (size_t)k * (3 * D_) + colOff + n;
    union { uint2 u; __half b[4]; } ph;
    ph.b[0] = __float2half_rn(v.x); ph.b[1] = __float2half_rn(v.y);
    ph.b[2] = __float2half_rn(v.z); ph.b[3] = __float2half_rn(v.w);
    *(uint2*)(hi + d) = ph.u;
}

// ---------------- layernorm: warp per row, no smem -----------------------------
__global__ __launch_bounds__(256)
void ln_k(const float* __restrict__ in, long in_stride,
          const float* __restrict__ w, const float* __restrict__ b,
          __half* __restrict__ oh, float* __restrict__ of, int nrows) {
    const int warp = threadIdx.x >> 5, lane = threadIdx.x & 31;
    const int row = blockIdx.x * 8 + warp;
    if (row >= nrows) return;
    const float* rp = in + (size_t)row * in_stride;

    float v[32];
    float s = 0.f;
    #pragma unroll
    for (int i = 0; i < 8; i++) {
        float4 t = *(const float4*)(rp + i * 128 + lane * 4);
        v[4 * i] = t.x; v[4 * i + 1] = t.y; v[4 * i + 2] = t.z; v[4 * i + 3] = t.w;
        s += t.x + t.y + t.z + t.w;
    }
    #pragma unroll
    for (int off = 16; off; off >>= 1) s += __shfl_xor_sync(0xffffffffu, s, off);
    const float mean = s * (1.0f / D_);

    float s2 = 0.f;
    #pragma unroll
    for (int i = 0; i < 32; i++) { float d = v[i] - mean; s2 += d * d; }
    #pragma unroll
    for (int off = 16; off; off >>= 1) s2 += __shfl_xor_sync(0xffffffffu, s2, off);
    const float inv = rsqrtf(s2 * (1.0f / D_) + 1e-5f);

    size_t base = (size_t)row * D_;
    #pragma unroll
    for (int i = 0; i < 8; i++) {
        int d = i * 128 + lane * 4;
        float4 wv = *(const float4*)(w + d);
        float4 bv = *(const float4*)(b + d);
        float o0 = (v[4 * i]     - mean) * inv * wv.x + bv.x;
        float o1 = (v[4 * i + 1] - mean) * inv * wv.y + bv.y;
        float o2 = (v[4 * i + 2] - mean) * inv * wv.z + bv.z;
        float o3 = (v[4 * i + 3] - mean) * inv * wv.w + bv.w;
        if (of) {
            float4 o4 = {o0, o1, o2, o3};
            *(float4*)(of + base + d) = o4;
        }
        if (oh) {
            uint2 u;
            u.x = pack_h2(o0, o1);
            u.y = pack_h2(o2, o3);
            *(uint2*)(oh + base + d) = u;
        }
    }
}

// ---------------- mma.sync fp16 GEMM, BMx128x32, 3-stage, 2 CTA/SM -------------
// Warp tiles 32m x (128/WN)n: BM128 -> 8 warps as 4x2 (32x64), BM64 -> 2x4 (32x32)
#define B_TILE 8704                         // 32 rows x 272B

template<int MODE, int BM>
__global__ __launch_bounds__(256, 2)
void gemm_tc(const __half* __restrict__ A, const __half* __restrict__ Bw,
             const float* __restrict__ bias0, const float* __restrict__ bias1,
             const float* __restrict__ bias2, const float* __restrict__ res,
             float* __restrict__ Cf, __half* __restrict__ Ch,
             __half* p0, __half* p1, __half* p2,
             int Kdim, int Nb, int Nout) {
    constexpr int A_TILE = BM * 80;
    constexpr int STAGE  = A_TILE + B_TILE;
    constexpr int WM  = BM / 32;            // warps along M
    constexpr int WN  = 8 / WM;             // warps along N
    constexpr int WTN = 128 / WN;           // warp n-extent (64 or 32)
    constexpr int NI  = WTN / 8;            // n fragments (8 or 4)
    constexpr int NG  = WTN / 16;           // B ldsm groups (4 or 2)

    extern __shared__ char smem[];
    const uint32_t sb = smem_u32(smem);
    const int tid = threadIdx.x, lane = tid & 31, wid = tid >> 5;
    const int bm = blockIdx.y * BM, bn = blockIdx.x * 128;
    const int wm = wid % WM, wn = wid / WM;

    const int KT = Kdim >> 5;

    auto load_stage = [&](int ss) {
        const uint32_t dst = sb + (ss % 3) * STAGE;
        const int kg = ss * 32;
        #pragma unroll
        for (int i = 0; i < BM / 64; i++) {
            int ch = tid + 256 * i;
            int r = ch >> 2;
            const __half* ga = A + (size_t)(bm + r) * Kdim + kg + (ch & 3) * 8;
            CP_ASYNC16(dst + r * 80 + (ch & 3) * 16, ga);
        }
        #pragma unroll
        for (int i = 0; i < 2; i++) {
            int ch = tid + 256 * i;
            int r = ch >> 4, c = (ch & 15) * 8;
            const __half* gb = Bw + (size_t)(kg + r) * Nb + bn + c;
            CP_ASYNC16(dst + A_TILE + r * 272 + (ch & 15) * 16, gb);
        }
    };

    load_stage(0); CP_COMMIT();
    load_stage(1); CP_COMMIT();

    float acc[2][NI][4] = {};

    for (int s = 0; s < KT; s++) {
        if (s == KT - 1) { CP_WAIT0(); } else { CP_WAIT1(); }
        __syncthreads();
        if (s + 2 < KT) { load_stage(s + 2); CP_COMMIT(); }

        const uint32_t base = sb + (s % 3) * STAGE;
        #pragma unroll
        for (int ks = 0; ks < 2; ks++) {
            uint32_t ah[2][4], bh[NG][4];
            #pragma unroll
            for (int mi = 0; mi < 2; mi++) {
                uint32_t ra = base + (wm * 32 + mi * 16 + (lane & 15)) * 80
                            + ks * 32 + (lane >> 4) * 16;
                LDSM4(ah[mi], ra);
            }
            #pragma unroll
            for (int g = 0; g < NG; g++) {
                uint32_t rb = base + A_TILE + (ks * 16 + (lane & 15)) * 272
                            + (wn * WTN + g * 16) * 2 + (lane >> 4) * 16;
                LDSM4T(bh[g], rb);
            }
            #pragma unroll
            for (int mi = 0; mi < 2; mi++)
                #pragma unroll
                for (int ni = 0; ni < NI; ni++) {
                    const uint32_t* bhp = &bh[ni >> 1][(ni & 1) * 2];
                    MMA_F16(acc[mi][ni], ah[mi], bhp);
                }
        }
    }

    // epilogue
    #pragma unroll
    for (int mi = 0; mi < 2; mi++) {
        const int r0 = bm + wm * 32 + mi * 16 + (lane >> 2);
        #pragma unroll
        for (int rr = 0; rr < 2; rr++) {
            const int m = r0 + rr * 8;
            const int bt = m >> 10, tt = m & (T_ - 1);
            #pragma unroll
            for (int ni = 0; ni < NI; ni++) {
                const int cc = bn + wn * WTN + ni * 8 + (lane & 3) * 2;
                float v0 = acc[mi][ni][rr * 2 + 0];
                float v1 = acc[mi][ni][rr * 2 + 1];
                if (MODE == 0) {
                    const int which = cc >> 10;
                    const int nn = cc & 1023;
                    const float* bp = (which == 0) ? bias0 : (which == 1 ? bias1 : bias2);
                    const int h = nn >> 6, hd = nn & 63;
                    const int bh_ = bt * H_ + h;
                    v0 += bp[nn]; v1 += bp[nn + 1];
                    if (which == 0) { v0 *= 0.125f; v1 *= 0.125f; }
                    __half2 hh;
                    hh.x = __float2half_rn(v0); hh.y = __float2half_rn(v1);
                    __half* dst = (which == 0) ? p0 : (which == 1 ? p1 : p2);
                    size_t o = ((size_t)bh_ * T_ + tt) * HD_ + hd;
                    *(__half2*)(dst + o) = hh;
                } else if (MODE == 1) {
                    size_t idx = (size_t)m * Nout + cc;
                    float2 bv = *(const float2*)(bias0 + cc);
                    float2 rv = *(const float2*)(res + idx);
                    float2 o2 = {v0 + bv.x + rv.x, v1 + bv.y + rv.y};
                    *(float2*)(Cf + idx) = o2;
                } else {
                    size_t idx = (size_t)m * Nout + cc;
                    float2 bv = *(const float2*)(bias0 + cc);
                    __half2 hh;
                    hh.x = __float2half_rn(fmaxf(v0 + bv.x, 0.f));
                    hh.y = __float2half_rn(fmaxf(v1 + bv.y, 0.f));
                    *(__half2*)(Ch + idx) = hh;
                }
            }
        }
    }
}

// ---------------- tensor-core flash attention ----------------------------------
#define APAD 72
#define ATILE_H (64 * APAD)
#define ATT_SMEM (3 * ATILE_H * 2)   // 27648 bytes

__global__ __launch_bounds__(128)
void attn_k(const __half* __restrict__ qg, const __half* __restrict__ kg,
            const __half* __restrict__ vg, __half* __restrict__ oh) {
    extern __shared__ __half as_[];
    __half* Qs = as_;
    __half* Ks = Qs + ATILE_H;
    __half* Vs = Ks + ATILE_H;

    const int tid = threadIdx.x, lane = tid & 31, warp = tid >> 5;
    const int bh = blockIdx.y;
    const int qt = gridDim.x - 1 - blockIdx.x;   // heavy tiles first
    const int q0 = qt * 64;
    const int b = bh >> 4, h = bh & 15;

    #pragma unroll
    for (int i = 0; i < 4; i++) {
        int ch = tid + 128 * i;
        int r = ch >> 3, c = (ch & 7) * 8;
        *(uint4*)&Qs[r * APAD + c] =
            *(const uint4*)(qg + ((size_t)bh * T_ + q0 + r) * HD_ + c);
    }
    __syncthreads();

    uint32_t aq[4][4];
    const uint32_t qbase = smem_u32(Qs);
    #pragma unroll
    for (int kf = 0; kf < 4; kf++) {
        uint32_t ra = qbase + ((warp * 16 + (lane & 15)) * APAD + kf * 16 + (lane >> 4) * 8) * 2;
        LDSM4(aq[kf], ra);
    }

    float mx[2] = {-1e30f, -1e30f}, lsum[2] = {0.f, 0.f};
    float oacc[8][4] = {};

    const uint32_t kbase = smem_u32(Ks);
    const uint32_t vbase = smem_u32(Vs);
    const int ntiles = qt + 1;

    for (int jt = 0; jt < ntiles; jt++) {
        const int j0 = jt * 64;
        __syncthreads();
        #pragma unroll
        for (int i = 0; i < 4; i++) {
            int ch = tid + 128 * i;
            int r = ch >> 3, c = (ch & 7) * 8;
            size_t g = ((size_t)bh * T_ + j0 + r) * HD_ + c;
            *(uint4*)&Ks[r * APAD + c] = *(const uint4*)(kg + g);
            *(uint4*)&Vs[r * APAD + c] = *(const uint4*)(vg + g);
        }
        __syncthreads();

        float sacc[8][4] = {};
        #pragma unroll
        for (int g = 0; g < 4; g++) {
            #pragma unroll
            for (int kf = 0; kf < 4; kf++) {
                uint32_t kb[4];
                uint32_t rb = kbase + ((g * 16 + (lane & 15)) * APAD + kf * 16 + (lane >> 4) * 8) * 2;
                LDSM4(kb, rb);
                MMA_F16_2(sacc[2 * g],     aq[kf], kb[0], kb[2]);
                MMA_F16_2(sacc[2 * g + 1], aq[kf], kb[1], kb[3]);
            }
        }

        if (jt == qt) {
            const int rbase = q0 + warp * 16 + (lane >> 2);
            #pragma unroll
            for (int nf = 0; nf < 8; nf++) {
                int c0 = j0 + nf * 8 + (lane & 3) * 2;
                if (c0     > rbase)     sacc[nf][0] = -1e30f;
                if (c0 + 1 > rbase)     sacc[nf][1] = -1e30f;
                if (c0     > rbase + 8) sacc[nf][2] = -1e30f;
                if (c0 + 1 > rbase + 8) sacc[nf][3] = -1e30f;
            }
        }

        #pragma unroll
        for (int hf = 0; hf < 2; hf++) {
            float mnew = -1e30f;
            #pragma unroll
            for (int nf = 0; nf < 8; nf++)
                mnew = fmaxf(mnew, fmaxf(sacc[nf][hf * 2], sacc[nf][hf * 2 + 1]));
            mnew = fmaxf(mnew, __shfl_xor_sync(0xffffffffu, mnew, 1));
            mnew = fmaxf(mnew, __shfl_xor_sync(0xffffffffu, mnew, 2));
            float mn = fmaxf(mx[hf], mnew);
            float corr = __expf(mx[hf] - mn);
            float ps = 0.f;
            #pragma unroll
            for (int nf = 0; nf < 8; nf++) {
                float s0 = __expf(sacc[nf][hf * 2]     - mn);
                float s1 = __expf(sacc[nf][hf * 2 + 1] - mn);
                sacc[nf][hf * 2] = s0; sacc[nf][hf * 2 + 1] = s1;
                ps += s0 + s1;
            }
            ps += __shfl_xor_sync(0xffffffffu, ps, 1);
            ps += __shfl_xor_sync(0xffffffffu, ps, 2);
            lsum[hf] = lsum[hf] * corr + ps;
            #pragma unroll
            for (int nf = 0; nf < 8; nf++) {
                oacc[nf][hf * 2] *= corr; oacc[nf][hf * 2 + 1] *= corr;
            }
            mx[hf] = mn;
        }

        uint32_t pah[4][4];
        #pragma unroll
        for (int kf = 0; kf < 4; kf++) {
            const float* s0 = sacc[2 * kf];
            const float* s1 = sacc[2 * kf + 1];
            pah[kf][0] = pack_h2(s0[0], s0[1]);
            pah[kf][1] = pack_h2(s0[2], s0[3]);
            pah[kf][2] = pack_h2(s1[0], s1[1]);
            pah[kf][3] = pack_h2(s1[2], s1[3]);
        }

        #pragma unroll
        for (int kf = 0; kf < 4; kf++) {
            #pragma unroll
            for (int g = 0; g < 4; g++) {
                uint32_t vb2[4];
                uint32_t rb = vbase + ((kf * 16 + (lane & 15)) * APAD + g * 16 + (lane >> 4) * 8) * 2;
                LDSM4T(vb2, rb);
                MMA_F16(oacc[2 * g],     pah[kf], vb2);
                MMA_F16(oacc[2 * g + 1], pah[kf], vb2 + 2);
            }
        }
    }

    #pragma unroll
    for (int hf = 0; hf < 2; hf++) {
        float inv = 1.0f / lsum[hf];
        int row = q0 + warp * 16 + (lane >> 2) + hf * 8;
        size_t rbase = ((size_t)(b * T_ + row)) * D_ + h * HD_;
        #pragma unroll
        for (int nf = 0; nf < 8; nf++) {
            int col = nf * 8 + (lane & 3) * 2;
            __half2 o2;
            o2.x = __float2half_rn(oacc[nf][hf * 2]     * inv);
            o2.y = __float2half_rn(oacc[nf][hf * 2 + 1] * inv);
            *(__half2*)(oh + rbase + col) = o2;
        }
    }
}

// ---------------- head GEMV ------------------------------------------------------
__global__ __launch_bounds__(256)
void head_k(const float* __restrict__ hf, const float* __restrict__ W,
            const float* __restrict__ hb, float* __restrict__ out) {
    __shared__ float s0[D_];
    __shared__ float s1[D_];
    for (int i = threadIdx.x; i < D_; i += 256) { s0[i] = hf[i]; s1[i] = hf[D_ + i]; }
    __syncthreads();
    int vcol = blockIdx.x * 256 + threadIdx.x;
    float a0 = 0.f, a1 = 0.f;
    #pragma unroll 4
    for (int d = 0; d < D_; d++) {
        float wv = W[(size_t)d * V_ + vcol];
        a0 += s0[d] * wv;
        a1 += s1[d] * wv;
    }
    float bb = hb[vcol];
    out[vcol]      = a0 + bb;
    out[V_ + vcol] = a1 + bb;
}

// ---------------- launch --------------------------------------------------
extern "C" void kernel_launch(void* const* d_in, const int* in_sizes, int n_in,
                              void* d_out, int out_size) {
    const int*   idx    = (const int*)  d_in[0];
    const float* tok    = (const float*)d_in[1];
    const float* pos    = (const float*)d_in[2];
    const float* ln1w   = (const float*)d_in[3];
    const float* ln1b   = (const float*)d_in[4];
    const float* qw     = (const float*)d_in[5];
    const float* qb     = (const float*)d_in[6];
    const float* kw     = (const float*)d_in[7];
    const float* kbi    = (const float*)d_in[8];
    const float* vw     = (const float*)d_in[9];
    const float* vb     = (const float*)d_in[10];
    const float* ow     = (const float*)d_in[11];
    const float* ob     = (const float*)d_in[12];
    const float* ln2w   = (const float*)d_in[13];
    const float* ln2b   = (const float*)d_in[14];
    const float* f1w    = (const float*)d_in[15];
    const float* f1b    = (const float*)d_in[16];
    const float* f2w    = (const float*)d_in[17];
    const float* f2b    = (const float*)d_in[18];
    const float* lnfw   = (const float*)d_in[19];
    const float* lnfb   = (const float*)d_in[20];
    const float* headw  = (const float*)d_in[21];
    const float* headb  = (const float*)d_in[22];

    float *x, *hf;
    __half *wqkv, *wo, *wf1, *wf2, *q, *k, *v, *hh, *oh, *ffh;
    cudaGetSymbolAddress((void**)&x,    g_x);
    cudaGetSymbolAddress((void**)&hf,   g_hf);
    cudaGetSymbolAddress((void**)&wqkv, g_wqkv);
    cudaGetSymbolAddress((void**)&wo,   g_wo);
    cudaGetSymbolAddress((void**)&wf1,  g_wf1);
    cudaGetSymbolAddress((void**)&wf2,  g_wf2);
    cudaGetSymbolAddress((void**)&q,    g_q);
    cudaGetSymbolAddress((void**)&k,    g_k);
    cudaGetSymbolAddress((void**)&v,    g_v);
    cudaGetSymbolAddress((void**)&hh,   g_hh);
    cudaGetSymbolAddress((void**)&oh,   g_oh);
    cudaGetSymbolAddress((void**)&ffh,  g_ffh);

    const int GS128 = 3 * (128 * 80 + B_TILE);   // 56832
    const int GS64  = 3 * (64 * 80 + B_TILE);    // 41472
    cudaFuncSetAttribute(gemm_tc<0, 128>, cudaFuncAttributeMaxDynamicSharedMemorySize, GS128);
    cudaFuncSetAttribute(gemm_tc<1, 64>,  cudaFuncAttributeMaxDynamicSharedMemorySize, GS64);
    cudaFuncSetAttribute(gemm_tc<2, 128>, cudaFuncAttributeMaxDynamicSharedMemorySize, GS128);
    cudaFuncSetAttribute(attn_k, cudaFuncAttributeMaxDynamicSharedMemorySize, ATT_SMEM);

    const long MEG = 1024 * 1024;
    dim3 gQKV(24, 16), gDD(8, 32), gF1(32, 16);
    dim3 gAt(T_ / 64, B_ * H_);

    // our launch 0..3; harness prepends 2 -> gemm lands at global index 5 for ncu
    embed_k<<<M_, 256>>>(idx, tok, pos);                                  // 0
    convqkv<<<dim3(1024, L_, 3), 256>>>(qw, kw, vw, wqkv);                // 1
    ln_k<<<M_ / 8, 256>>>(x, D_, ln1w, ln1b, hh, nullptr, M_);            // 2
    gemm_tc<0, 128><<<gQKV, 256, GS128>>>(hh, wqkv, qb, kbi, vb, nullptr, // 3
                                          nullptr, nullptr, q, k, v, D_, 3 * D_, 0);
    convw1<<<(L_ * MEG) / 2048, 256>>>(ow,  wo);
    convw1<<<(L_ * 4 * MEG) / 2048, 256>>>(f1w, wf1);
    convw1<<<(L_ * 4 * MEG) / 2048, 256>>>(f2w, wf2);

    for (int l = 0; l < L_; l++) {
        size_t wq3 = (size_t)l * 3 * MEG;
        size_t wdd = (size_t)l * MEG;
        size_t wff = (size_t)l * 4 * MEG;

        if (l > 0) {
            ln_k<<<M_ / 8, 256>>>(x, D_, ln1w + l * D_, ln1b + l * D_, hh, nullptr, M_);
            gemm_tc<0, 128><<<gQKV, 256, GS128>>>(hh, wqkv + wq3,
                                                  qb + l * D_, kbi + l * D_, vb + l * D_,
                                                  nullptr, nullptr, nullptr,
                                                  q, k, v, D_, 3 * D_, 0);
        }

        attn_k<<<gAt, 128, ATT_SMEM>>>(q, k, v, oh);

        gemm_tc<1, 64><<<gDD, 256, GS64>>>(oh, wo + wdd,
                                           ob + l * D_, nullptr, nullptr, x,
                                           x, nullptr, nullptr, nullptr, nullptr,
                                           D_, D_, D_);

        ln_k<<<M_ / 8, 256>>>(x, D_, ln2w + l * D_, ln2b + l * D_, hh, nullptr, M_);

        gemm_tc<2, 128><<<gF1, 256, GS128>>>(hh, wf1 + wff,
                                             f1b + l * FF_, nullptr, nullptr, nullptr,
                                             nullptr, ffh, nullptr, nullptr, nullptr,
                                             D_, FF_, FF_);

        gemm_tc<1, 64><<<gDD, 256, GS64>>>(ffh, wf2 + wff,
                                           f2b + l * D_, nullptr, nullptr, x,
                                           x, nullptr, nullptr, nullptr, nullptr,
                                           FF_, D_, D_);
    }

    ln_k<<<1, 256>>>(x + (size_t)(T_ - 1) * D_, (long)T_ * D_, lnfw, lnfb,
                     nullptr, hf, B_);

    head_k<<<V_ / 256, 256>>>(hf, headw, headb, (float*)d_out);
}

// round 12
// speedup vs baseline: 1.0369x; 1.0332x over previous
#include <cuda_runtime.h>
#include <cuda_fp16.h>
#include <cstdint>

#define D_  1024
#define H_  16
#define HD_ 64
#define T_  1024
#define B_  2
#define L_  8
#define FF_ 4096
#define V_  32000
#define M_  (B_ * T_)   // 2048 rows

// ---------------- scratch (device globals) ----------------------------------
__device__ __half g_wqkv[(size_t)L_ * D_ * 3 * D_];
__device__ __half g_wo  [(size_t)L_ * D_ * D_];
__device__ __half g_wf1 [(size_t)L_ * D_ * FF_];
__device__ __half g_wf2 [(size_t)L_ * FF_ * D_];
__device__ float g_x [M_ * D_];
__device__ __half g_q[M_ * D_];   // [BH,T,HD], pre-scaled
__device__ __half g_k[M_ * D_];   // [BH,T,HD]
__device__ __half g_v[M_ * D_];   // [BH,T,HD]
__device__ __half g_hh [M_ * D_];
__device__ __half g_oh [M_ * D_];
__device__ __half g_ffh[M_ * FF_];
__device__ float g_hf[B_ * D_];

// ---------------- ptx helpers ------------------------------------------------
__device__ __forceinline__ uint32_t smem_u32(const void* p) {
    uint32_t a;
    asm("{ .reg .u64 t; cvta.to.shared.u64 t, %1; cvt.u32.u64 %0, t; }" : "=r"(a) : "l"(p));
    return a;
}
#define LDSM4(r, a) \
    asm volatile("ldmatrix.sync.aligned.m8n8.x4.shared.b16 {%0,%1,%2,%3}, [%4];" \
        : "=r"((r)[0]), "=r"((r)[1]), "=r"((r)[2]), "=r"((r)[3]) : "r"(a))
#define LDSM4T(r, a) \
    asm volatile("ldmatrix.sync.aligned.m8n8.x4.trans.shared.b16 {%0,%1,%2,%3}, [%4];" \
        : "=r"((r)[0]), "=r"((r)[1]), "=r"((r)[2]), "=r"((r)[3]) : "r"(a))
#define MMA_F16(c, a, b) \
    asm volatile("mma.sync.aligned.m16n8k16.row.col.f32.f16.f16.f32 " \
        "{%0,%1,%2,%3}, {%4,%5,%6,%7}, {%8,%9}, {%0,%1,%2,%3};" \
        : "+f"((c)[0]), "+f"((c)[1]), "+f"((c)[2]), "+f"((c)[3]) \
        : "r"((a)[0]), "r"((a)[1]), "r"((a)[2]), "r"((a)[3]), "r"((b)[0]), "r"((b)[1]))
#define MMA_F16_2(c, a, b0, b1) \
    asm volatile("mma.sync.aligned.m16n8k16.row.col.f32.f16.f16.f32 " \
        "{%0,%1,%2,%3}, {%4,%5,%6,%7}, {%8,%9}, {%0,%1,%2,%3};" \
        : "+f"((c)[0]), "+f"((c)[1]), "+f"((c)[2]), "+f"((c)[3]) \
        : "r"((a)[0]), "r"((a)[1]), "r"((a)[2]), "r"((a)[3]), "r"(b0), "r"(b1))
#define CP_ASYNC16(d, g) \
    asm volatile("cp.async.cg.shared.global [%0], [%1], 16;" :: "r"(d), "l"(g))
#define CP_COMMIT() asm volatile("cp.async.commit_group;" ::: "memory")
#define CP_WAIT0()  asm volatile("cp.async.wait_group 0;" ::: "memory")
#define CP_WAIT1()  asm volatile("cp.async.wait_group 1;" ::: "memory")

__device__ __forceinline__ uint32_t pack_h2(float a, float b) {
    __half2 h; h.x = __float2half_rn(a); h.y = __float2half_rn(b);
    return *(uint32_t*)&h;
}

// ---------------- embedding ---------------------------------------------------
__global__ void embed_k(const int* __restrict__ idx,
                        const float* __restrict__ tok,
                        const float* __restrict__ pos) {
    int m = blockIdx.x;
    int t = m & (T_ - 1);
    const float* te = tok + (size_t)idx[m] * D_;
    const float* pe = pos + (size_t)t * D_;
    float* xr = g_x + (size_t)m * D_;
    for (int d = threadIdx.x; d < D_; d += blockDim.x)
        xr[d] = te[d] + pe[d];
}

// ---------------- weight convert ----------------------------------------------
__global__ void convw1(const float* __restrict__ W, __half* __restrict__ hi) {
    size_t idx = ((size_t)blockIdx.x * 256 + threadIdx.x) * 8;
    float4 v0 = *(const float4*)(W + idx);
    float4 v1 = *(const float4*)(W + idx + 4);
    union { uint4 u; __half b[8]; } ph;
    ph.b[0] = __float2half_rn(v0.x); ph.b[1] = __float2half_rn(v0.y);
    ph.b[2] = __float2half_rn(v0.z); ph.b[3] = __float2half_rn(v0.w);
    ph.b[4] = __float2half_rn(v1.x); ph.b[5] = __float2half_rn(v1.y);
    ph.b[6] = __float2half_rn(v1.z); ph.b[7] = __float2half_rn(v1.w);
    *(uint4*)(hi + idx) = ph.u;
}

// merged QKV conversion: z selects source (0=q,1=k,2=v), y = layer
__global__ void convqkv(const float* __restrict__ qw, const float* __restrict__ kw,
                        const float* __restrict__ vw, __half* __restrict__ hi) {
    const float* W = (blockIdx.z == 0) ? qw : (blockIdx.z == 1 ? kw : vw);
    const int colOff = blockIdx.z << 10;
    long z = blockIdx.y;
    long idx = ((long)blockIdx.x * 256 + threadIdx.x) * 4;
    int k = (int)(idx >> 10);
    int n = (int)(idx & 1023);
    float4 v = *(const float4*)(W + z * (1 << 20) + idx);
    size_t d = (size_t)z * (3 << 20) + (size_t)k * (3 * D_) + colOff + n;
    union { uint2 u; __half b[4]; } ph;
    ph.b[0] = __float2half_rn(v.x); ph.b[1] = __float2half_rn(v.y);
    ph.b[2] = __float2half_rn(v.z); ph.b[3] = __float2half_rn(v.w);
    *(uint2*)(hi + d) = ph.u;
}

// ---------------- layernorm: warp per row, no smem -----------------------------
__global__ __launch_bounds__(256)
void ln_k(const float* __restrict__ in, long in_stride,
          const float* __restrict__ w, const float* __restrict__ b,
          __half* __restrict__ oh, float* __restrict__ of, int nrows) {
    const int warp = threadIdx.x >> 5, lane = threadIdx.x & 31;
    const int row = blockIdx.x * 8 + warp;
    if (row >= nrows) return;
    const float* rp = in + (size_t)row * in_stride;

    float v[32];
    float s = 0.f;
    #pragma unroll
    for (int i = 0; i < 8; i++) {
        float4 t = *(const float4*)(rp + i * 128 + lane * 4);
        v[4 * i] = t.x; v[4 * i + 1] = t.y; v[4 * i + 2] = t.z; v[4 * i + 3] = t.w;
        s += t.x + t.y + t.z + t.w;
    }
    #pragma unroll
    for (int off = 16; off; off >>= 1) s += __shfl_xor_sync(0xffffffffu, s, off);
    const float mean = s * (1.0f / D_);

    float s2 = 0.f;
    #pragma unroll
    for (int i = 0; i < 32; i++) { float d = v[i] - mean; s2 += d * d; }
    #pragma unroll
    for (int off = 16; off; off >>= 1) s2 += __shfl_xor_sync(0xffffffffu, s2, off);
    const float inv = rsqrtf(s2 * (1.0f / D_) + 1e-5f);

    size_t base = (size_t)row * D_;
    #pragma unroll
    for (int i = 0; i < 8; i++) {
        int d = i * 128 + lane * 4;
        float4 wv = *(const float4*)(w + d);
        float4 bv = *(const float4*)(b + d);
        float o0 = (v[4 * i]     - mean) * inv * wv.x + bv.x;
        float o1 = (v[4 * i + 1] - mean) * inv * wv.y + bv.y;
        float o2 = (v[4 * i + 2] - mean) * inv * wv.z + bv.z;
        float o3 = (v[4 * i + 3] - mean) * inv * wv.w + bv.w;
        if (of) {
            float4 o4 = {o0, o1, o2, o3};
            *(float4*)(of + base + d) = o4;
        }
        if (oh) {
            uint2 u;
            u.x = pack_h2(o0, o1);
            u.y = pack_h2(o2, o3);
            *(uint2*)(oh + base + d) = u;
        }
    }
}

// ---------------- mma.sync fp16 GEMM (256 thr), BMx128x32, 3-stage, 2 CTA/SM ---
#define B_TILE 8704                         // 32 rows x 272B

template<int MODE, int BM>
__global__ __launch_bounds__(256, 2)
void gemm_tc(const __half* __restrict__ A, const __half* __restrict__ Bw,
             const float* __restrict__ bias0, const float* __restrict__ bias1,
             const float* __restrict__ bias2, const float* __restrict__ res,
             float* __restrict__ Cf, __half* __restrict__ Ch,
             __half* p0, __half* p1, __half* p2,
             int Kdim, int Nb, int Nout) {
    constexpr int A_TILE = BM * 80;
    constexpr int STAGE  = A_TILE + B_TILE;
    constexpr int WM  = BM / 32;            // warps along M
    constexpr int WN  = 8 / WM;             // warps along N
    constexpr int WTN = 128 / WN;           // warp n-extent
    constexpr int NI  = WTN / 8;
    constexpr int NG  = WTN / 16;

    extern __shared__ char smem[];
    const uint32_t sb = smem_u32(smem);
    const int tid = threadIdx.x, lane = tid & 31, wid = tid >> 5;
    const int bm = blockIdx.y * BM, bn = blockIdx.x * 128;
    const int wm = wid % WM, wn = wid / WM;

    const int KT = Kdim >> 5;

    auto load_stage = [&](int ss) {
        const uint32_t dst = sb + (ss % 3) * STAGE;
        const int kg = ss * 32;
        #pragma unroll
        for (int i = 0; i < BM / 64; i++) {
            int ch = tid + 256 * i;
            int r = ch >> 2;
            const __half* ga = A + (size_t)(bm + r) * Kdim + kg + (ch & 3) * 8;
            CP_ASYNC16(dst + r * 80 + (ch & 3) * 16, ga);
        }
        #pragma unroll
        for (int i = 0; i < 2; i++) {
            int ch = tid + 256 * i;
            int r = ch >> 4, c = (ch & 15) * 8;
            const __half* gb = Bw + (size_t)(kg + r) * Nb + bn + c;
            CP_ASYNC16(dst + A_TILE + r * 272 + (ch & 15) * 16, gb);
        }
    };

    load_stage(0); CP_COMMIT();
    load_stage(1); CP_COMMIT();

    float acc[2][NI][4] = {};

    for (int s = 0; s < KT; s++) {
        if (s == KT - 1) { CP_WAIT0(); } else { CP_WAIT1(); }
        __syncthreads();
        if (s + 2 < KT) { load_stage(s + 2); CP_COMMIT(); }

        const uint32_t base = sb + (s % 3) * STAGE;
        #pragma unroll
        for (int ks = 0; ks < 2; ks++) {
            uint32_t ah[2][4], bh[NG][4];
            #pragma unroll
            for (int mi = 0; mi < 2; mi++) {
                uint32_t ra = base + (wm * 32 + mi * 16 + (lane & 15)) * 80
                            + ks * 32 + (lane >> 4) * 16;
                LDSM4(ah[mi], ra);
            }
            #pragma unroll
            for (int g = 0; g < NG; g++) {
                uint32_t rb = base + A_TILE + (ks * 16 + (lane & 15)) * 272
                            + (wn * WTN + g * 16) * 2 + (lane >> 4) * 16;
                LDSM4T(bh[g], rb);
            }
            #pragma unroll
            for (int mi = 0; mi < 2; mi++)
                #pragma unroll
                for (int ni = 0; ni < NI; ni++) {
                    const uint32_t* bhp = &bh[ni >> 1][(ni & 1) * 2];
                    MMA_F16(acc[mi][ni], ah[mi], bhp);
                }
        }
    }

    // epilogue
    #pragma unroll
    for (int mi = 0; mi < 2; mi++) {
        const int r0 = bm + wm * 32 + mi * 16 + (lane >> 2);
        #pragma unroll
        for (int rr = 0; rr < 2; rr++) {
            const int m = r0 + rr * 8;
            const int bt = m >> 10, tt = m & (T_ - 1);
            #pragma unroll
            for (int ni = 0; ni < NI; ni++) {
                const int cc = bn + wn * WTN + ni * 8 + (lane & 3) * 2;
                float v0 = acc[mi][ni][rr * 2 + 0];
                float v1 = acc[mi][ni][rr * 2 + 1];
                if (MODE == 0) {
                    const int which = cc >> 10;
                    const int nn = cc & 1023;
                    const float* bp = (which == 0) ? bias0 : (which == 1 ? bias1 : bias2);
                    const int h = nn >> 6, hd = nn & 63;
                    const int bh_ = bt * H_ + h;
                    v0 += bp[nn]; v1 += bp[nn + 1];
                    if (which == 0) { v0 *= 0.125f; v1 *= 0.125f; }
                    __half2 hh;
                    hh.x = __float2half_rn(v0); hh.y = __float2half_rn(v1);
                    __half* dst = (which == 0) ? p0 : (which == 1 ? p1 : p2);
                    size_t o = ((size_t)bh_ * T_ + tt) * HD_ + hd;
                    *(__half2*)(dst + o) = hh;
                } else if (MODE == 1) {
                    size_t idx = (size_t)m * Nout + cc;
                    float2 bv = *(const float2*)(bias0 + cc);
                    float2 rv = *(const float2*)(res + idx);
                    float2 o2 = {v0 + bv.x + rv.x, v1 + bv.y + rv.y};
                    *(float2*)(Cf + idx) = o2;
                } else {
                    size_t idx = (size_t)m * Nout + cc;
                    float2 bv = *(const float2*)(bias0 + cc);
                    __half2 hh;
                    hh.x = __float2half_rn(fmaxf(v0 + bv.x, 0.f));
                    hh.y = __float2half_rn(fmaxf(v1 + bv.y, 0.f));
                    *(__half2*)(Ch + idx) = hh;
                }
            }
        }
    }
}

// ------------- gemm128: 128 thr, 4 warps (2x2), warp tile 64x64, 128x128x32 ----
// Higher smem intensity: 4KB LDSM per 128 KFLOP per warp k-step.
// MODE 2 only (F1: relu fp16 out).
__global__ __launch_bounds__(128, 2)
void gemm128_f1(const __half* __restrict__ A, const __half* __restrict__ Bw,
                const float* __restrict__ bias0, __half* __restrict__ Ch,
                int Kdim, int Nb, int Nout) {
    constexpr int A_TILE = 128 * 80;
    constexpr int STAGE  = A_TILE + B_TILE;

    extern __shared__ char smem[];
    const uint32_t sb = smem_u32(smem);
    const int tid = threadIdx.x, lane = tid & 31, wid = tid >> 5;
    const int bm = blockIdx.y * 128, bn = blockIdx.x * 128;
    const int wm = wid & 1, wn = wid >> 1;   // 2x2 warps, each 64x64

    const int KT = Kdim >> 5;

    auto load_stage = [&](int ss) {
        const uint32_t dst = sb + (ss % 3) * STAGE;
        const int kg = ss * 32;
        #pragma unroll
        for (int i = 0; i < 4; i++) {
            int ch = tid + 128 * i;            // 512 A chunks
            int r = ch >> 2;
            const __half* ga = A + (size_t)(bm + r) * Kdim + kg + (ch & 3) * 8;
            CP_ASYNC16(dst + r * 80 + (ch & 3) * 16, ga);
        }
        #pragma unroll
        for (int i = 0; i < 4; i++) {
            int ch = tid + 128 * i;            // 512 B chunks
            int r = ch >> 4, c = (ch & 15) * 8;
            const __half* gb = Bw + (size_t)(kg + r) * Nb + bn + c;
            CP_ASYNC16(dst + A_TILE + r * 272 + (ch & 15) * 16, gb);
        }
    };

    load_stage(0); CP_COMMIT();
    load_stage(1); CP_COMMIT();

    float acc[4][8][4] = {};

    for (int s = 0; s < KT; s++) {
        if (s == KT - 1) { CP_WAIT0(); } else { CP_WAIT1(); }
        __syncthreads();
        if (s + 2 < KT) { load_stage(s + 2); CP_COMMIT(); }

        const uint32_t base = sb + (s % 3) * STAGE;
        #pragma unroll
        for (int ks = 0; ks < 2; ks++) {
            uint32_t ah[4][4], bh[4][4];
            #pragma unroll
            for (int mi = 0; mi < 4; mi++) {
                uint32_t ra = base + (wm * 64 + mi * 16 + (lane & 15)) * 80
                            + ks * 32 + (lane >> 4) * 16;
                LDSM4(ah[mi], ra);
            }
            #pragma unroll
            for (int g = 0; g < 4; g++) {
                uint32_t rb = base + A_TILE + (ks * 16 + (lane & 15)) * 272
                            + (wn * 64 + g * 16) * 2 + (lane >> 4) * 16;
                LDSM4T(bh[g], rb);
            }
            #pragma unroll
            for (int mi = 0; mi < 4; mi++)
                #pragma unroll
                for (int ni = 0; ni < 8; ni++) {
                    const uint32_t* bhp = &bh[ni >> 1][(ni & 1) * 2];
                    MMA_F16(acc[mi][ni], ah[mi], bhp);
                }
        }
    }

    // epilogue: relu -> fp16
    #pragma unroll
    for (int mi = 0; mi < 4; mi++) {
        const int r0 = bm + wm * 64 + mi * 16 + (lane >> 2);
        #pragma unroll
        for (int rr = 0; rr < 2; rr++) {
            const int m = r0 + rr * 8;
            #pragma unroll
            for (int ni = 0; ni < 8; ni++) {
                const int cc = bn + wn * 64 + ni * 8 + (lane & 3) * 2;
                float v0 = acc[mi][ni][rr * 2 + 0];
                float v1 = acc[mi][ni][rr * 2 + 1];
                size_t idx = (size_t)m * Nout + cc;
                float2 bv = *(const float2*)(bias0 + cc);
                __half2 hh;
                hh.x = __float2half_rn(fmaxf(v0 + bv.x, 0.f));
                hh.y = __float2half_rn(fmaxf(v1 + bv.y, 0.f));
                *(__half2*)(Ch + idx) = hh;
            }
        }
    }
}

// ---------------- tensor-core flash attention ----------------------------------
#define APAD 72
#define ATILE_H (64 * APAD)
#define ATT_SMEM (3 * ATILE_H * 2)   // 27648 bytes

__global__ __launch_bounds__(128)
void attn_k(const __half* __restrict__ qg, const __half* __restrict__ kg,
            const __half* __restrict__ vg, __half* __restrict__ oh) {
    extern __shared__ __half as_[];
    __half* Qs = as_;
    __half* Ks = Qs + ATILE_H;
    __half* Vs = Ks + ATILE_H;

    const int tid = threadIdx.x, lane = tid & 31, warp = tid >> 5;
    const int bh = blockIdx.y;
    const int qt = gridDim.x - 1 - blockIdx.x;   // heavy tiles first
    const int q0 = qt * 64;
    const int b = bh >> 4, h = bh & 15;

    #pragma unroll
    for (int i = 0; i < 4; i++) {
        int ch = tid + 128 * i;
        int r = ch >> 3, c = (ch & 7) * 8;
        *(uint4*)&Qs[r * APAD + c] =
            *(const uint4*)(qg + ((size_t)bh * T_ + q0 + r) * HD_ + c);
    }
    __syncthreads();

    uint32_t aq[4][4];
    const uint32_t qbase = smem_u32(Qs);
    #pragma unroll
    for (int kf = 0; kf < 4; kf++) {
        uint32_t ra = qbase + ((warp * 16 + (lane & 15)) * APAD + kf * 16 + (lane >> 4) * 8) * 2;
        LDSM4(aq[kf], ra);
    }

    float mx[2] = {-1e30f, -1e30f}, lsum[2] = {0.f, 0.f};
    float oacc[8][4] = {};

    const uint32_t kbase = smem_u32(Ks);
    const uint32_t vbase = smem_u32(Vs);
    const int ntiles = qt + 1;

    for (int jt = 0; jt < ntiles; jt++) {
        const int j0 = jt * 64;
        __syncthreads();
        #pragma unroll
        for (int i = 0; i < 4; i++) {
            int ch = tid + 128 * i;
            int r = ch >> 3, c = (ch & 7) * 8;
            size_t g = ((size_t)bh * T_ + j0 + r) * HD_ + c;
            *(uint4*)&Ks[r * APAD + c] = *(const uint4*)(kg + g);
            *(uint4*)&Vs[r * APAD + c] = *(const uint4*)(vg + g);
        }
        __syncthreads();

        float sacc[8][4] = {};
        #pragma unroll
        for (int g = 0; g < 4; g++) {
            #pragma unroll
            for (int kf = 0; kf < 4; kf++) {
                uint32_t kb[4];
                uint32_t rb = kbase + ((g * 16 + (lane & 15)) * APAD + kf * 16 + (lane >> 4) * 8) * 2;
                LDSM4(kb, rb);
                MMA_F16_2(sacc[2 * g],     aq[kf], kb[0], kb[2]);
                MMA_F16_2(sacc[2 * g + 1], aq[kf], kb[1], kb[3]);
            }
        }

        if (jt == qt) {
            const int rbase = q0 + warp * 16 + (lane >> 2);
            #pragma unroll
            for (int nf = 0; nf < 8; nf++) {
                int c0 = j0 + nf * 8 + (lane & 3) * 2;
                if (c0     > rbase)     sacc[nf][0] = -1e30f;
                if (c0 + 1 > rbase)     sacc[nf][1] = -1e30f;
                if (c0     > rbase + 8) sacc[nf][2] = -1e30f;
                if (c0 + 1 > rbase + 8) sacc[nf][3] = -1e30f;
            }
        }

        #pragma unroll
        for (int hf = 0; hf < 2; hf++) {
            float mnew = -1e30f;
            #pragma unroll
            for (int nf = 0; nf < 8; nf++)
                mnew = fmaxf(mnew, fmaxf(sacc[nf][hf * 2], sacc[nf][hf * 2 + 1]));
            mnew = fmaxf(mnew, __shfl_xor_sync(0xffffffffu, mnew, 1));
            mnew = fmaxf(mnew, __shfl_xor_sync(0xffffffffu, mnew, 2));
            float mn = fmaxf(mx[hf], mnew);
            float corr = __expf(mx[hf] - mn);
            float ps = 0.f;
            #pragma unroll
            for (int nf = 0; nf < 8; nf++) {
                float s0 = __expf(sacc[nf][hf * 2]     - mn);
                float s1 = __expf(sacc[nf][hf * 2 + 1] - mn);
                sacc[nf][hf * 2] = s0; sacc[nf][hf * 2 + 1] = s1;
                ps += s0 + s1;
            }
            ps += __shfl_xor_sync(0xffffffffu, ps, 1);
            ps += __shfl_xor_sync(0xffffffffu, ps, 2);
            lsum[hf] = lsum[hf] * corr + ps;
            #pragma unroll
            for (int nf = 0; nf < 8; nf++) {
                oacc[nf][hf * 2] *= corr; oacc[nf][hf * 2 + 1] *= corr;
            }
            mx[hf] = mn;
        }

        uint32_t pah[4][4];
        #pragma unroll
        for (int kf = 0; kf < 4; kf++) {
            const float* s0 = sacc[2 * kf];
            const float* s1 = sacc[2 * kf + 1];
            pah[kf][0] = pack_h2(s0[0], s0[1]);
            pah[kf][1] = pack_h2(s0[2], s0[3]);
            pah[kf][2] = pack_h2(s1[0], s1[1]);
            pah[kf][3] = pack_h2(s1[2], s1[3]);
        }

        #pragma unroll
        for (int kf = 0; kf < 4; kf++) {
            #pragma unroll
            for (int g = 0; g < 4; g++) {
                uint32_t vb2[4];
                uint32_t rb = vbase + ((kf * 16 + (lane & 15)) * APAD + g * 16 + (lane >> 4) * 8) * 2;
                LDSM4T(vb2, rb);
                MMA_F16(oacc[2 * g],     pah[kf], vb2);
                MMA_F16(oacc[2 * g + 1], pah[kf], vb2 + 2);
            }
        }
    }

    #pragma unroll
    for (int hf = 0; hf < 2; hf++) {
        float inv = 1.0f / lsum[hf];
        int row = q0 + warp * 16 + (lane >> 2) + hf * 8;
        size_t rbase = ((size_t)(b * T_ + row)) * D_ + h * HD_;
        #pragma unroll
        for (int nf = 0; nf < 8; nf++) {
            int col = nf * 8 + (lane & 3) * 2;
            __half2 o2;
            o2.x = __float2half_rn(oacc[nf][hf * 2]     * inv);
            o2.y = __float2half_rn(oacc[nf][hf * 2 + 1] * inv);
            *(__half2*)(oh + rbase + col) = o2;
        }
    }
}

// ---------------- head GEMV ------------------------------------------------------
__global__ __launch_bounds__(256)
void head_k(const float* __restrict__ hf, const float* __restrict__ W,
            const float* __restrict__ hb, float* __restrict__ out) {
    __shared__ float s0[D_];
    __shared__ float s1[D_];
    for (int i = threadIdx.x; i < D_; i += 256) { s0[i] = hf[i]; s1[i] = hf[D_ + i]; }
    __syncthreads();
    int vcol = blockIdx.x * 256 + threadIdx.x;
    float a0 = 0.f, a1 = 0.f;
    #pragma unroll 4
    for (int d = 0; d < D_; d++) {
        float wv = W[(size_t)d * V_ + vcol];
        a0 += s0[d] * wv;
        a1 += s1[d] * wv;
    }
    float bb = hb[vcol];
    out[vcol]      = a0 + bb;
    out[V_ + vcol] = a1 + bb;
}

// ---------------- launch --------------------------------------------------
extern "C" void kernel_launch(void* const* d_in, const int* in_sizes, int n_in,
                              void* d_out, int out_size) {
    const int*   idx    = (const int*)  d_in[0];
    const float* tok    = (const float*)d_in[1];
    const float* pos    = (const float*)d_in[2];
    const float* ln1w   = (const float*)d_in[3];
    const float* ln1b   = (const float*)d_in[4];
    const float* qw     = (const float*)d_in[5];
    const float* qb     = (const float*)d_in[6];
    const float* kw     = (const float*)d_in[7];
    const float* kbi    = (const float*)d_in[8];
    const float* vw     = (const float*)d_in[9];
    const float* vb     = (const float*)d_in[10];
    const float* ow     = (const float*)d_in[11];
    const float* ob     = (const float*)d_in[12];
    const float* ln2w   = (const float*)d_in[13];
    const float* ln2b   = (const float*)d_in[14];
    const float* f1w    = (const float*)d_in[15];
    const float* f1b    = (const float*)d_in[16];
    const float* f2w    = (const float*)d_in[17];
    const float* f2b    = (const float*)d_in[18];
    const float* lnfw   = (const float*)d_in[19];
    const float* lnfb   = (const float*)d_in[20];
    const float* headw  = (const float*)d_in[21];
    const float* headb  = (const float*)d_in[22];

    float *x, *hf;
    __half *wqkv, *wo, *wf1, *wf2, *q, *k, *v, *hh, *oh, *ffh;
    cudaGetSymbolAddress((void**)&x,    g_x);
    cudaGetSymbolAddress((void**)&hf,   g_hf);
    cudaGetSymbolAddress((void**)&wqkv, g_wqkv);
    cudaGetSymbolAddress((void**)&wo,   g_wo);
    cudaGetSymbolAddress((void**)&wf1,  g_wf1);
    cudaGetSymbolAddress((void**)&wf2,  g_wf2);
    cudaGetSymbolAddress((void**)&q,    g_q);
    cudaGetSymbolAddress((void**)&k,    g_k);
    cudaGetSymbolAddress((void**)&v,    g_v);
    cudaGetSymbolAddress((void**)&hh,   g_hh);
    cudaGetSymbolAddress((void**)&oh,   g_oh);
    cudaGetSymbolAddress((void**)&ffh,  g_ffh);

    const int GS64  = 3 * (64 * 80 + B_TILE);    // 41472
    const int GS128 = 3 * (128 * 80 + B_TILE);   // 56832
    cudaFuncSetAttribute(gemm_tc<0, 64>, cudaFuncAttributeMaxDynamicSharedMemorySize, GS64);
    cudaFuncSetAttribute(gemm_tc<1, 64>, cudaFuncAttributeMaxDynamicSharedMemorySize, GS64);
    cudaFuncSetAttribute(gemm128_f1,     cudaFuncAttributeMaxDynamicSharedMemorySize, GS128);
    cudaFuncSetAttribute(attn_k, cudaFuncAttributeMaxDynamicSharedMemorySize, ATT_SMEM);

    const long MEG = 1024 * 1024;
    dim3 gQKV(24, 32), gDD(8, 32), gF1(32, 16);
    dim3 gAt(T_ / 64, B_ * H_);

    // our launch 0..3; harness prepends 2 -> gemm lands at global index 5 for ncu
    embed_k<<<M_, 256>>>(idx, tok, pos);                                  // 0
    convqkv<<<dim3(1024, L_, 3), 256>>>(qw, kw, vw, wqkv);                // 1
    ln_k<<<M_ / 8, 256>>>(x, D_, ln1w, ln1b, hh, nullptr, M_);            // 2
    gemm_tc<0, 64><<<gQKV, 256, GS64>>>(hh, wqkv, qb, kbi, vb, nullptr,   // 3
                                        nullptr, nullptr, q, k, v, D_, 3 * D_, 0);
    convw1<<<(L_ * MEG) / 2048, 256>>>(ow,  wo);
    convw1<<<(L_ * 4 * MEG) / 2048, 256>>>(f1w, wf1);
    convw1<<<(L_ * 4 * MEG) / 2048, 256>>>(f2w, wf2);

    for (int l = 0; l < L_; l++) {
        size_t wq3 = (size_t)l * 3 * MEG;
        size_t wdd = (size_t)l * MEG;
        size_t wff = (size_t)l * 4 * MEG;

        if (l > 0) {
            ln_k<<<M_ / 8, 256>>>(x, D_, ln1w + l * D_, ln1b + l * D_, hh, nullptr, M_);
            gemm_tc<0, 64><<<gQKV, 256, GS64>>>(hh, wqkv + wq3,
                                                qb + l * D_, kbi + l * D_, vb + l * D_,
                                                nullptr, nullptr, nullptr,
                                                q, k, v, D_, 3 * D_, 0);
        }

        attn_k<<<gAt, 128, ATT_SMEM>>>(q, k, v, oh);

        gemm_tc<1, 64><<<gDD, 256, GS64>>>(oh, wo + wdd,
                                           ob + l * D_, nullptr, nullptr, x,
                                           x, nullptr, nullptr, nullptr, nullptr,
                                           D_, D_, D_);

        ln_k<<<M_ / 8, 256>>>(x, D_, ln2w + l * D_, ln2b + l * D_, hh, nullptr, M_);

        gemm128_f1<<<gF1, 128, GS128>>>(hh, wf1 + wff, f1b + l * FF_, ffh,
                                        D_, FF_, FF_);

        gemm_tc<1, 64><<<gDD, 256, GS64>>>(ffh, wf2 + wff,
                                           f2b + l * D_, nullptr, nullptr, x,
                                           x, nullptr, nullptr, nullptr, nullptr,
                                           FF_, D_, D_);
    }

    ln_k<<<1, 256>>>(x + (size_t)(T_ - 1) * D_, (long)T_ * D_, lnfw, lnfb,
                     nullptr, hf, B_);

    head_k<<<V_ / 256, 256>>>(hf, headw, headb, (float*)d_out);
}